// round 10
// baseline (speedup 1.0000x reference)
#include <cuda_runtime.h>
#include <cstdint>
#include <cstddef>

#define NMAX 20000
#define EMAX 320000

// ---------------- scratch (device globals; no allocation allowed) ----------------
__device__ int   g_count[NMAX];
__device__ int   g_offs[NMAX + 1];
__device__ int   g_cursor[NMAX];
__device__ int   g_esrc[EMAX];      // CSR payload: src node id per edge slot
__device__ float g_feat1[NMAX * 256];
__device__ float g_el1[NMAX * 4];
__device__ float g_er1[NMAX * 4];
__device__ float g_h2[NMAX * 256];
__device__ float g_feat2[NMAX * 64];
__device__ float g_el2[NMAX];
__device__ float g_er2[NMAX];

// ---------------- packed f32x2 helpers ------------------------------------------
__device__ __forceinline__ unsigned long long pack2(float x, float y) {
    unsigned long long r;
    asm("mov.b64 %0, {%1, %2};" : "=l"(r) : "f"(x), "f"(y));
    return r;
}
__device__ __forceinline__ float2 unpack2(unsigned long long v) {
    float2 r;
    asm("mov.b64 {%0, %1}, %2;" : "=f"(r.x), "=f"(r.y) : "l"(v));
    return r;
}
#define FMA2(d, a, b) asm("fma.rn.f32x2 %0, %1, %2, %0;" : "+l"(d) : "l"(a), "l"(b))

// ---------------- CSR build ------------------------------------------------------
__global__ void hist_k(const int* __restrict__ dst, int E) {
    int e = (blockIdx.x * blockDim.x + threadIdx.x) * 2;
    if (e + 1 < E) {
        int d0 = dst[e], d1 = dst[e + 1];
        atomicAdd(&g_count[d0], 1);
        atomicAdd(&g_count[d1], 1);
    } else if (e < E) {
        atomicAdd(&g_count[dst[e]], 1);
    }
}

__global__ void scan_k(int n) {
    __shared__ int part[1024];
    int tid = threadIdx.x;
    int per = (n + 1023) >> 10;
    int base = tid * per;
    int sum = 0;
    for (int i = 0; i < per; i++) {
        int idx = base + i;
        if (idx < n) sum += g_count[idx];
    }
    part[tid] = sum;
    __syncthreads();
    for (int off = 1; off < 1024; off <<= 1) {
        int t = (tid >= off) ? part[tid - off] : 0;
        __syncthreads();
        part[tid] += t;
        __syncthreads();
    }
    int run = part[tid] - sum;
    for (int i = 0; i < per; i++) {
        int idx = base + i;
        if (idx < n) {
            g_offs[idx] = run;
            g_cursor[idx] = run;
            run += g_count[idx];
        }
    }
    if (tid == 1023) g_offs[n] = part[1023];
}

__global__ void scatter_k(const int* __restrict__ dst, const int* __restrict__ src, int E) {
    int e = (blockIdx.x * blockDim.x + threadIdx.x) * 2;
    if (e + 1 < E) {
        int d0 = dst[e], d1 = dst[e + 1];
        int s0 = src[e], s1 = src[e + 1];
        int p0 = atomicAdd(&g_cursor[d0], 1);
        int p1 = atomicAdd(&g_cursor[d1], 1);
        g_esrc[p0] = s0;
        g_esrc[p1] = s1;
    } else if (e < E) {
        int p = atomicAdd(&g_cursor[dst[e]], 1);
        g_esrc[p] = src[e];
    }
}

// ---------------- GEMM (128 x TN tile, 8x8 micro) + fused attention epilogue -----
// C[N,M] = A[N,K] @ B[K,M]. BK=16, register-staged prefetch of next K-chunk.
// 8x8 per-thread micro-tile: LDS bytes per FMA2 halved vs 4x4 (L1TEX was binding).
// Epilogue: each thread's 8 cols live in exactly one 64-wide head; partial dot
// with al/ar then 8-lane shfl reduction (offsets 4,2,1 stay inside the group).
template <int TN, int NT>
__global__ __launch_bounds__(NT) void gemm_attn_k(const float* __restrict__ A,
                                                  const float* __restrict__ B,
                                                  float* __restrict__ C,
                                                  const float* __restrict__ al,
                                                  const float* __restrict__ ar,
                                                  float* __restrict__ el,
                                                  float* __restrict__ er,
                                                  int N, int K, int M) {
    constexpr int TCD = TN / 8;                 // threads along cols (16 or 8)
    constexpr int NA4 = (128 * 16 / 4) / NT;    // A float4 loads per thread
    constexpr int NB4 = (16 * TN / 4) / NT;     // B float4 loads per thread
    __shared__ float As[16][128];               // transposed: As[k][row]
    __shared__ float Bs[16][TN];

    int tid = threadIdx.x;
    int tr = tid / TCD, tc = tid % TCD;
    int rowBase = blockIdx.y * 128, colBase = blockIdx.x * TN;

    unsigned long long acc[8][4];
#pragma unroll
    for (int m = 0; m < 8; m++)
#pragma unroll
        for (int p = 0; p < 4; p++) acc[m][p] = 0ull;

    float4 aReg[NA4], bReg[NB4];

    // prologue: load chunk 0 into registers
#pragma unroll
    for (int i = 0; i < NA4; i++) {
        int f4 = tid + i * NT;
        int arow = f4 >> 2, acol = (f4 & 3) << 2;
        int grow = rowBase + arow;
        aReg[i] = (grow < N) ? *(const float4*)&A[(size_t)grow * K + acol]
                             : make_float4(0.f, 0.f, 0.f, 0.f);
    }
#pragma unroll
    for (int i = 0; i < NB4; i++) {
        int f4 = tid + i * NT;
        int brow = f4 / (TN / 4), bcol = (f4 % (TN / 4)) << 2;
        bReg[i] = *(const float4*)&B[(size_t)brow * M + colBase + bcol];
    }

    int nChunks = K >> 4;
    for (int chunk = 0; chunk < nChunks; chunk++) {
        // stage registers -> smem
#pragma unroll
        for (int i = 0; i < NA4; i++) {
            int f4 = tid + i * NT;
            int arow = f4 >> 2, acol = (f4 & 3) << 2;
            As[acol + 0][arow] = aReg[i].x;
            As[acol + 1][arow] = aReg[i].y;
            As[acol + 2][arow] = aReg[i].z;
            As[acol + 3][arow] = aReg[i].w;
        }
#pragma unroll
        for (int i = 0; i < NB4; i++) {
            int f4 = tid + i * NT;
            int brow = f4 / (TN / 4), bcol = (f4 % (TN / 4)) << 2;
            *(float4*)&Bs[brow][bcol] = bReg[i];
        }
        __syncthreads();

        // prefetch next chunk (LDG issued before the compute block)
        if (chunk + 1 < nChunks) {
            int k0 = (chunk + 1) << 4;
#pragma unroll
            for (int i = 0; i < NA4; i++) {
                int f4 = tid + i * NT;
                int arow = f4 >> 2, acol = (f4 & 3) << 2;
                int grow = rowBase + arow;
                aReg[i] = (grow < N) ? *(const float4*)&A[(size_t)grow * K + k0 + acol]
                                     : make_float4(0.f, 0.f, 0.f, 0.f);
            }
#pragma unroll
            for (int i = 0; i < NB4; i++) {
                int f4 = tid + i * NT;
                int brow = f4 / (TN / 4), bcol = (f4 % (TN / 4)) << 2;
                bReg[i] = *(const float4*)&B[(size_t)(k0 + brow) * M + colBase + bcol];
            }
        }

#pragma unroll
        for (int k = 0; k < 16; k++) {
            float4 a0 = *(const float4*)&As[k][tr << 3];
            float4 a1 = *(const float4*)&As[k][(tr << 3) + 4];
            const unsigned long long* bp = (const unsigned long long*)&Bs[k][tc << 3];
            unsigned long long b0 = bp[0], b1 = bp[1], b2 = bp[2], b3 = bp[3];
            float av[8] = {a0.x, a0.y, a0.z, a0.w, a1.x, a1.y, a1.z, a1.w};
#pragma unroll
            for (int m = 0; m < 8; m++) {
                unsigned long long am = pack2(av[m], av[m]);
                FMA2(acc[m][0], am, b0);
                FMA2(acc[m][1], am, b1);
                FMA2(acc[m][2], am, b2);
                FMA2(acc[m][3], am, b3);
            }
        }
        __syncthreads();
    }

    // ---- epilogue: store C + fused attention scores ----
    int c0 = colBase + (tc << 3);
    int head = c0 >> 6;
    int H = M >> 6;
    float alv[8], arv[8];
#pragma unroll
    for (int j = 0; j < 8; j++) { alv[j] = al[c0 + j]; arv[j] = ar[c0 + j]; }

#pragma unroll
    for (int m = 0; m < 8; m++) {
        int row = rowBase + (tr << 3) + m;
        float2 q0 = unpack2(acc[m][0]);
        float2 q1 = unpack2(acc[m][1]);
        float2 q2 = unpack2(acc[m][2]);
        float2 q3 = unpack2(acc[m][3]);
        if (row < N) {
            *(float4*)&C[(size_t)row * M + c0]     = make_float4(q0.x, q0.y, q1.x, q1.y);
            *(float4*)&C[(size_t)row * M + c0 + 4] = make_float4(q2.x, q2.y, q3.x, q3.y);
        }
        float sl = q0.x * alv[0] + q0.y * alv[1] + q1.x * alv[2] + q1.y * alv[3]
                 + q2.x * alv[4] + q2.y * alv[5] + q3.x * alv[6] + q3.y * alv[7];
        float sr = q0.x * arv[0] + q0.y * arv[1] + q1.x * arv[2] + q1.y * arv[3]
                 + q2.x * arv[4] + q2.y * arv[5] + q3.x * arv[6] + q3.y * arv[7];
#pragma unroll
        for (int o = 4; o; o >>= 1) {
            sl += __shfl_xor_sync(0xffffffffu, sl, o);
            sr += __shfl_xor_sync(0xffffffffu, sr, o);
        }
        if ((tc & 7) == 0 && row < N) {
            el[row * H + head] = sl;
            er[row * H + head] = sr;
        }
    }
}

// ---------------- fused per-node softmax + aggregation + bias(+ELU) -------------
template <int H, bool DO_ELU>
__global__ __launch_bounds__(256) void node_agg_k(const float* __restrict__ feat,
                           const float* __restrict__ el,
                           const float* __restrict__ er,
                           const float* __restrict__ bias, float* __restrict__ out,
                           int N) {
    constexpr int F = H * 64;
    constexpr int FP = F / 32;
    int w = (blockIdx.x * blockDim.x + threadIdx.x) >> 5;
    int lane = threadIdx.x & 31;
    if (w >= N) return;
    int beg = g_offs[w], end = g_offs[w + 1];

    float erh[H];
#pragma unroll
    for (int h = 0; h < H; h++) erh[h] = er[w * H + h];

    // ---- pass A: per-head max, lane-parallel over edges ----
    float mx[H];
#pragma unroll
    for (int h = 0; h < H; h++) mx[h] = -1e30f;
    for (int i = beg + lane; i < end; i += 32) {
        int s = g_esrc[i];
        if (H == 4) {
            float4 t = *(const float4*)&el[s * 4];
            float ev[4] = {t.x, t.y, t.z, t.w};
#pragma unroll
            for (int h = 0; h < 4; h++) {
                float v = ev[h] + erh[h];
                v = v > 0.f ? v : 0.2f * v;
                mx[h] = fmaxf(mx[h], v);
            }
        } else {
            float v = el[s] + erh[0];
            v = v > 0.f ? v : 0.2f * v;
            mx[0] = fmaxf(mx[0], v);
        }
    }
#pragma unroll
    for (int o = 16; o; o >>= 1)
#pragma unroll
        for (int h = 0; h < H; h++) mx[h] = fmaxf(mx[h], __shfl_xor_sync(0xffffffffu, mx[h], o));

    // ---- pass B: serial over edges, software-pipelined (prefetch s and el) ----
    float den[H];
#pragma unroll
    for (int h = 0; h < H; h++) den[h] = 0.f;
    float acc[FP];
#pragma unroll
    for (int j = 0; j < FP; j++) acc[j] = 0.f;
    int hsel = (lane * FP) >> 6;

    int sNext = (beg < end) ? g_esrc[beg] : 0;
    float4 tNext = make_float4(0.f, 0.f, 0.f, 0.f);
    float eNext = 0.f;
    if (beg < end) {
        if (H == 4) tNext = *(const float4*)&el[sNext * 4];
        else        eNext = el[sNext];
    }

    for (int i = beg; i < end; i++) {
        int s = sNext;
        float4 t = tNext;
        float es = eNext;
        int inext = i + 1;
        if (inext < end) {
            sNext = g_esrc[inext];
            if (H == 4) tNext = *(const float4*)&el[sNext * 4];
            else        eNext = el[sNext];
        }

        float ex[H];
        if (H == 4) {
            float ev[4] = {t.x, t.y, t.z, t.w};
#pragma unroll
            for (int h = 0; h < 4; h++) {
                float v = ev[h] + erh[h];
                v = v > 0.f ? v : 0.2f * v;
                ex[h] = __expf(v - mx[h]);
                den[h] += ex[h];
            }
        } else {
            float v = es + erh[0];
            v = v > 0.f ? v : 0.2f * v;
            ex[0] = __expf(v - mx[0]);
            den[0] += ex[0];
        }
        const float* fs = feat + (size_t)s * F + lane * FP;
        if (FP == 8) {
            float4 f0 = *(const float4*)fs;
            float4 f1 = *(const float4*)(fs + 4);
            float a = ex[hsel];
            acc[0] += f0.x * a; acc[1] += f0.y * a; acc[2] += f0.z * a; acc[3] += f0.w * a;
            acc[4] += f1.x * a; acc[5] += f1.y * a; acc[6] += f1.z * a; acc[7] += f1.w * a;
        } else {
            float2 f0 = *(const float2*)fs;
            float a = ex[0];
            acc[0] += f0.x * a;
            acc[1] += f0.y * a;
        }
    }

    float inv = (end > beg) ? 1.f / den[hsel] : 0.f;
    float* po = out + (size_t)w * F + lane * FP;
#pragma unroll
    for (int j = 0; j < FP; j++) {
        float r = acc[j] * inv + bias[lane * FP + j];
        if (DO_ELU) r = r > 0.f ? r : expm1f(r);
        po[j] = r;
    }
}

// ---------------- launch ---------------------------------------------------------
extern "C" void kernel_launch(void* const* d_in, const int* in_sizes, int n_in,
                              void* d_out, int out_size) {
    const float* X   = (const float*)d_in[0];
    const float* W1  = (const float*)d_in[1];
    const float* al1 = (const float*)d_in[2];
    const float* ar1 = (const float*)d_in[3];
    const float* b1  = (const float*)d_in[4];
    const float* W2  = (const float*)d_in[5];
    const float* al2 = (const float*)d_in[6];
    const float* ar2 = (const float*)d_in[7];
    const float* b2  = (const float*)d_in[8];
    const int*   src = (const int*)d_in[9];
    const int*   dst = (const int*)d_in[10];
    float* out = (float*)d_out;

    int N = in_sizes[0] / 256;
    int E = in_sizes[9];

    void *p_count, *p_feat1, *p_el1, *p_er1, *p_h2, *p_feat2, *p_el2, *p_er2;
    cudaGetSymbolAddress(&p_count, g_count);
    cudaGetSymbolAddress(&p_feat1, g_feat1);
    cudaGetSymbolAddress(&p_el1, g_el1);
    cudaGetSymbolAddress(&p_er1, g_er1);
    cudaGetSymbolAddress(&p_h2, g_h2);
    cudaGetSymbolAddress(&p_feat2, g_feat2);
    cudaGetSymbolAddress(&p_el2, g_el2);
    cudaGetSymbolAddress(&p_er2, g_er2);

    // CSR build
    cudaMemsetAsync(p_count, 0, (size_t)N * sizeof(int));
    int eThreads = (E + 1) / 2;
    hist_k<<<(eThreads + 255) / 256, 256>>>(dst, E);
    scan_k<<<1, 1024>>>(N);
    scatter_k<<<(eThreads + 255) / 256, 256>>>(dst, src, E);

    int rowBlocks = (N + 127) / 128;

    // Layer 1: GEMM (M=256) + fused attention scores
    gemm_attn_k<128, 256><<<dim3(2, rowBlocks), 256>>>(X, W1, (float*)p_feat1, al1, ar1,
                                                       (float*)p_el1, (float*)p_er1,
                                                       N, 256, 256);
    node_agg_k<4, true><<<(N * 32 + 255) / 256, 256>>>(
        (const float*)p_feat1, (const float*)p_el1, (const float*)p_er1, b1,
        (float*)p_h2, N);

    // Layer 2: GEMM (M=64) + fused attention scores
    gemm_attn_k<64, 128><<<dim3(1, rowBlocks), 128>>>((const float*)p_h2, W2,
                                                      (float*)p_feat2, al2, ar2,
                                                      (float*)p_el2, (float*)p_er2,
                                                      N, 256, 64);
    node_agg_k<1, false><<<(N * 32 + 255) / 256, 256>>>(
        (const float*)p_feat2, (const float*)p_el2, (const float*)p_er2, b2, out, N);
}

// round 15
// speedup vs baseline: 1.1064x; 1.1064x over previous
#include <cuda_runtime.h>
#include <cstdint>
#include <cstddef>

#define NMAX 20000
#define EMAX 320000

// ---------------- scratch (device globals; no allocation allowed) ----------------
__device__ int   g_count[NMAX];
__device__ int   g_offs[NMAX + 1];
__device__ int   g_cursor[NMAX];
__device__ int   g_esrc[EMAX];      // CSR payload: src node id per edge slot
__device__ float g_feat1[NMAX * 256];
__device__ float g_el1[NMAX * 4];
__device__ float g_er1[NMAX * 4];
__device__ float g_h2[NMAX * 256];
__device__ float g_feat2[NMAX * 64];
__device__ float g_el2[NMAX];
__device__ float g_er2[NMAX];

// ---------------- packed f32x2 helpers ------------------------------------------
__device__ __forceinline__ unsigned long long pack2(float x, float y) {
    unsigned long long r;
    asm("mov.b64 %0, {%1, %2};" : "=l"(r) : "f"(x), "f"(y));
    return r;
}
__device__ __forceinline__ float2 unpack2(unsigned long long v) {
    float2 r;
    asm("mov.b64 {%0, %1}, %2;" : "=f"(r.x), "=f"(r.y) : "l"(v));
    return r;
}
#define FMA2(d, a, b) asm("fma.rn.f32x2 %0, %1, %2, %0;" : "+l"(d) : "l"(a), "l"(b))

// ---------------- CSR build ------------------------------------------------------
__global__ void hist_k(const int* __restrict__ dst, int E) {
    int e = (blockIdx.x * blockDim.x + threadIdx.x) * 2;
    if (e + 1 < E) {
        int d0 = dst[e], d1 = dst[e + 1];
        atomicAdd(&g_count[d0], 1);
        atomicAdd(&g_count[d1], 1);
    } else if (e < E) {
        atomicAdd(&g_count[dst[e]], 1);
    }
}

__global__ void scan_k(int n) {
    __shared__ int part[1024];
    int tid = threadIdx.x;
    int per = (n + 1023) >> 10;
    int base = tid * per;
    int sum = 0;
    for (int i = 0; i < per; i++) {
        int idx = base + i;
        if (idx < n) sum += g_count[idx];
    }
    part[tid] = sum;
    __syncthreads();
    for (int off = 1; off < 1024; off <<= 1) {
        int t = (tid >= off) ? part[tid - off] : 0;
        __syncthreads();
        part[tid] += t;
        __syncthreads();
    }
    int run = part[tid] - sum;
    for (int i = 0; i < per; i++) {
        int idx = base + i;
        if (idx < n) {
            g_offs[idx] = run;
            g_cursor[idx] = run;
            run += g_count[idx];
        }
    }
    if (tid == 1023) g_offs[n] = part[1023];
}

__global__ void scatter_k(const int* __restrict__ dst, const int* __restrict__ src, int E) {
    int e = (blockIdx.x * blockDim.x + threadIdx.x) * 2;
    if (e + 1 < E) {
        int d0 = dst[e], d1 = dst[e + 1];
        int s0 = src[e], s1 = src[e + 1];
        int p0 = atomicAdd(&g_cursor[d0], 1);
        int p1 = atomicAdd(&g_cursor[d1], 1);
        g_esrc[p0] = s0;
        g_esrc[p1] = s1;
    } else if (e < E) {
        int p = atomicAdd(&g_cursor[dst[e]], 1);
        g_esrc[p] = src[e];
    }
}

// ---------------- GEMM (128x64 tile, 8x4 micro, row-pair packed) + attn epilogue --
// C[N,M] = A[N,K] @ B[K,M]. 256 threads, BK=16, register prefetch of next chunk.
// Per-thread: 8 rows (4 packed row-PAIRS straight out of As, no pack instr)
// x 4 cols (B values duplicated into both f32x2 lanes, 4 packs per k-iter).
// acc[c][p].lo = C[2p][c], .hi = C[2p+1][c]. 3 LDS.128 + 4 mov + 16 FMA2 / k-iter.
// Each block covers exactly ONE 64-col head; epilogue reduces el/er over the
// 16-lane tr-group (aligned half-warp; shfl 8/4/2/1 stays inside).
__global__ __launch_bounds__(256, 3) void gemm_attn_k(const float* __restrict__ A,
                                                      const float* __restrict__ B,
                                                      float* __restrict__ C,
                                                      const float* __restrict__ al,
                                                      const float* __restrict__ ar,
                                                      float* __restrict__ el,
                                                      float* __restrict__ er,
                                                      int N, int K, int M) {
    __shared__ float As[16][128];   // transposed: As[k][row]; row pairs adjacent
    __shared__ float Bs[16][64];

    int tid = threadIdx.x;
    int tr = tid >> 4, tc = tid & 15;           // 16 x 16 threads
    int rowBase = blockIdx.y * 128, colBase = blockIdx.x * 64;

    unsigned long long acc[4][4];               // [col][rowpair]
#pragma unroll
    for (int c = 0; c < 4; c++)
#pragma unroll
        for (int p = 0; p < 4; p++) acc[c][p] = 0ull;

    float4 aReg[2], bReg;

    // prologue: chunk 0 -> registers
#pragma unroll
    for (int i = 0; i < 2; i++) {
        int f4 = tid + i * 256;
        int arow = f4 >> 2, acol = (f4 & 3) << 2;
        int grow = rowBase + arow;
        aReg[i] = (grow < N) ? *(const float4*)&A[(size_t)grow * K + acol]
                             : make_float4(0.f, 0.f, 0.f, 0.f);
    }
    {
        int brow = tid >> 4, bcol = (tid & 15) << 2;
        bReg = *(const float4*)&B[(size_t)brow * M + colBase + bcol];
    }

    int nChunks = K >> 4;
    for (int chunk = 0; chunk < nChunks; chunk++) {
        // stage registers -> smem
#pragma unroll
        for (int i = 0; i < 2; i++) {
            int f4 = tid + i * 256;
            int arow = f4 >> 2, acol = (f4 & 3) << 2;
            As[acol + 0][arow] = aReg[i].x;
            As[acol + 1][arow] = aReg[i].y;
            As[acol + 2][arow] = aReg[i].z;
            As[acol + 3][arow] = aReg[i].w;
        }
        {
            int brow = tid >> 4, bcol = (tid & 15) << 2;
            *(float4*)&Bs[brow][bcol] = bReg;
        }
        __syncthreads();

        // prefetch next chunk
        if (chunk + 1 < nChunks) {
            int k0 = (chunk + 1) << 4;
#pragma unroll
            for (int i = 0; i < 2; i++) {
                int f4 = tid + i * 256;
                int arow = f4 >> 2, acol = (f4 & 3) << 2;
                int grow = rowBase + arow;
                aReg[i] = (grow < N) ? *(const float4*)&A[(size_t)grow * K + k0 + acol]
                                     : make_float4(0.f, 0.f, 0.f, 0.f);
            }
            {
                int brow = tid >> 4, bcol = (tid & 15) << 2;
                bReg = *(const float4*)&B[(size_t)(k0 + brow) * M + colBase + bcol];
            }
        }

#pragma unroll
        for (int k = 0; k < 16; k++) {
            // 8 rows = 4 row-pairs, loaded packed (rows adjacent in As[k][])
            const unsigned long long* ap = (const unsigned long long*)&As[k][tr << 3];
            unsigned long long a0 = ap[0], a1 = ap[1], a2 = ap[2], a3 = ap[3];
            float4 bv = *(const float4*)&Bs[k][tc << 2];
            unsigned long long bd0 = pack2(bv.x, bv.x);
            unsigned long long bd1 = pack2(bv.y, bv.y);
            unsigned long long bd2 = pack2(bv.z, bv.z);
            unsigned long long bd3 = pack2(bv.w, bv.w);
            FMA2(acc[0][0], a0, bd0); FMA2(acc[0][1], a1, bd0);
            FMA2(acc[0][2], a2, bd0); FMA2(acc[0][3], a3, bd0);
            FMA2(acc[1][0], a0, bd1); FMA2(acc[1][1], a1, bd1);
            FMA2(acc[1][2], a2, bd1); FMA2(acc[1][3], a3, bd1);
            FMA2(acc[2][0], a0, bd2); FMA2(acc[2][1], a1, bd2);
            FMA2(acc[2][2], a2, bd2); FMA2(acc[2][3], a3, bd2);
            FMA2(acc[3][0], a0, bd3); FMA2(acc[3][1], a1, bd3);
            FMA2(acc[3][2], a2, bd3); FMA2(acc[3][3], a3, bd3);
        }
        __syncthreads();
    }

    // ---- epilogue: store C + fused attention scores ----
    int c0 = colBase + (tc << 2);
    int head = colBase >> 6;        // whole block is one head (TN=64)
    int H = M >> 6;
    float al0 = al[c0], al1v = al[c0 + 1], al2v = al[c0 + 2], al3 = al[c0 + 3];
    float ar0 = ar[c0], ar1v = ar[c0 + 1], ar2v = ar[c0 + 2], ar3 = ar[c0 + 3];

#pragma unroll
    for (int p = 0; p < 4; p++) {
        float2 q0 = unpack2(acc[0][p]);
        float2 q1 = unpack2(acc[1][p]);
        float2 q2 = unpack2(acc[2][p]);
        float2 q3 = unpack2(acc[3][p]);
        int row0 = rowBase + (tr << 3) + (p << 1);
        int row1 = row0 + 1;
        if (row0 < N) *(float4*)&C[(size_t)row0 * M + c0] = make_float4(q0.x, q1.x, q2.x, q3.x);
        if (row1 < N) *(float4*)&C[(size_t)row1 * M + c0] = make_float4(q0.y, q1.y, q2.y, q3.y);

        float sl0 = q0.x * al0 + q1.x * al1v + q2.x * al2v + q3.x * al3;
        float sr0 = q0.x * ar0 + q1.x * ar1v + q2.x * ar2v + q3.x * ar3;
        float sl1 = q0.y * al0 + q1.y * al1v + q2.y * al2v + q3.y * al3;
        float sr1 = q0.y * ar0 + q1.y * ar1v + q2.y * ar2v + q3.y * ar3;
#pragma unroll
        for (int o = 8; o; o >>= 1) {
            sl0 += __shfl_xor_sync(0xffffffffu, sl0, o);
            sr0 += __shfl_xor_sync(0xffffffffu, sr0, o);
            sl1 += __shfl_xor_sync(0xffffffffu, sl1, o);
            sr1 += __shfl_xor_sync(0xffffffffu, sr1, o);
        }
        if (tc == 0) {
            if (row0 < N) { el[row0 * H + head] = sl0; er[row0 * H + head] = sr0; }
            if (row1 < N) { el[row1 * H + head] = sl1; er[row1 * H + head] = sr1; }
        }
    }
}

// ---------------- fused per-node softmax + aggregation + bias(+ELU) -------------
template <int H, bool DO_ELU>
__global__ __launch_bounds__(256) void node_agg_k(const float* __restrict__ feat,
                           const float* __restrict__ el,
                           const float* __restrict__ er,
                           const float* __restrict__ bias, float* __restrict__ out,
                           int N) {
    constexpr int F = H * 64;
    constexpr int FP = F / 32;
    int w = (blockIdx.x * blockDim.x + threadIdx.x) >> 5;
    int lane = threadIdx.x & 31;
    if (w >= N) return;
    int beg = g_offs[w], end = g_offs[w + 1];

    float erh[H];
#pragma unroll
    for (int h = 0; h < H; h++) erh[h] = er[w * H + h];

    // ---- pass A: per-head max, lane-parallel over edges ----
    float mx[H];
#pragma unroll
    for (int h = 0; h < H; h++) mx[h] = -1e30f;
    for (int i = beg + lane; i < end; i += 32) {
        int s = g_esrc[i];
        if (H == 4) {
            float4 t = *(const float4*)&el[s * 4];
            float ev[4] = {t.x, t.y, t.z, t.w};
#pragma unroll
            for (int h = 0; h < 4; h++) {
                float v = ev[h] + erh[h];
                v = v > 0.f ? v : 0.2f * v;
                mx[h] = fmaxf(mx[h], v);
            }
        } else {
            float v = el[s] + erh[0];
            v = v > 0.f ? v : 0.2f * v;
            mx[0] = fmaxf(mx[0], v);
        }
    }
#pragma unroll
    for (int o = 16; o; o >>= 1)
#pragma unroll
        for (int h = 0; h < H; h++) mx[h] = fmaxf(mx[h], __shfl_xor_sync(0xffffffffu, mx[h], o));

    // ---- pass B: serial over edges, software-pipelined (prefetch s and el) ----
    float den[H];
#pragma unroll
    for (int h = 0; h < H; h++) den[h] = 0.f;
    float acc[FP];
#pragma unroll
    for (int j = 0; j < FP; j++) acc[j] = 0.f;
    int hsel = (lane * FP) >> 6;

    int sNext = (beg < end) ? g_esrc[beg] : 0;
    float4 tNext = make_float4(0.f, 0.f, 0.f, 0.f);
    float eNext = 0.f;
    if (beg < end) {
        if (H == 4) tNext = *(const float4*)&el[sNext * 4];
        else        eNext = el[sNext];
    }

    for (int i = beg; i < end; i++) {
        int s = sNext;
        float4 t = tNext;
        float es = eNext;
        int inext = i + 1;
        if (inext < end) {
            sNext = g_esrc[inext];
            if (H == 4) tNext = *(const float4*)&el[sNext * 4];
            else        eNext = el[sNext];
        }

        float ex[H];
        if (H == 4) {
            float ev[4] = {t.x, t.y, t.z, t.w};
#pragma unroll
            for (int h = 0; h < 4; h++) {
                float v = ev[h] + erh[h];
                v = v > 0.f ? v : 0.2f * v;
                ex[h] = __expf(v - mx[h]);
                den[h] += ex[h];
            }
        } else {
            float v = es + erh[0];
            v = v > 0.f ? v : 0.2f * v;
            ex[0] = __expf(v - mx[0]);
            den[0] += ex[0];
        }
        const float* fs = feat + (size_t)s * F + lane * FP;
        if (FP == 8) {
            float4 f0 = *(const float4*)fs;
            float4 f1 = *(const float4*)(fs + 4);
            float a = ex[hsel];
            acc[0] += f0.x * a; acc[1] += f0.y * a; acc[2] += f0.z * a; acc[3] += f0.w * a;
            acc[4] += f1.x * a; acc[5] += f1.y * a; acc[6] += f1.z * a; acc[7] += f1.w * a;
        } else {
            float2 f0 = *(const float2*)fs;
            float a = ex[0];
            acc[0] += f0.x * a;
            acc[1] += f0.y * a;
        }
    }

    float inv = (end > beg) ? 1.f / den[hsel] : 0.f;
    float* po = out + (size_t)w * F + lane * FP;
#pragma unroll
    for (int j = 0; j < FP; j++) {
        float r = acc[j] * inv + bias[lane * FP + j];
        if (DO_ELU) r = r > 0.f ? r : expm1f(r);
        po[j] = r;
    }
}

// ---------------- launch ---------------------------------------------------------
extern "C" void kernel_launch(void* const* d_in, const int* in_sizes, int n_in,
                              void* d_out, int out_size) {
    const float* X   = (const float*)d_in[0];
    const float* W1  = (const float*)d_in[1];
    const float* al1 = (const float*)d_in[2];
    const float* ar1 = (const float*)d_in[3];
    const float* b1  = (const float*)d_in[4];
    const float* W2  = (const float*)d_in[5];
    const float* al2 = (const float*)d_in[6];
    const float* ar2 = (const float*)d_in[7];
    const float* b2  = (const float*)d_in[8];
    const int*   src = (const int*)d_in[9];
    const int*   dst = (const int*)d_in[10];
    float* out = (float*)d_out;

    int N = in_sizes[0] / 256;
    int E = in_sizes[9];

    void *p_count, *p_feat1, *p_el1, *p_er1, *p_h2, *p_feat2, *p_el2, *p_er2;
    cudaGetSymbolAddress(&p_count, g_count);
    cudaGetSymbolAddress(&p_feat1, g_feat1);
    cudaGetSymbolAddress(&p_el1, g_el1);
    cudaGetSymbolAddress(&p_er1, g_er1);
    cudaGetSymbolAddress(&p_h2, g_h2);
    cudaGetSymbolAddress(&p_feat2, g_feat2);
    cudaGetSymbolAddress(&p_el2, g_el2);
    cudaGetSymbolAddress(&p_er2, g_er2);

    // CSR build
    cudaMemsetAsync(p_count, 0, (size_t)N * sizeof(int));
    int eThreads = (E + 1) / 2;
    hist_k<<<(eThreads + 255) / 256, 256>>>(dst, E);
    scan_k<<<1, 1024>>>(N);
    scatter_k<<<(eThreads + 255) / 256, 256>>>(dst, src, E);

    int rowBlocks = (N + 127) / 128;

    // Layer 1: GEMM (M=256) + fused attention scores
    gemm_attn_k<<<dim3(4, rowBlocks), 256>>>(X, W1, (float*)p_feat1, al1, ar1,
                                             (float*)p_el1, (float*)p_er1, N, 256, 256);
    node_agg_k<4, true><<<(N * 32 + 255) / 256, 256>>>(
        (const float*)p_feat1, (const float*)p_el1, (const float*)p_er1, b1,
        (float*)p_h2, N);

    // Layer 2: GEMM (M=64) + fused attention scores
    gemm_attn_k<<<dim3(1, rowBlocks), 256>>>((const float*)p_h2, W2, (float*)p_feat2,
                                             al2, ar2, (float*)p_el2, (float*)p_er2,
                                             N, 256, 64);
    node_agg_k<1, false><<<(N * 32 + 255) / 256, 256>>>(
        (const float*)p_feat2, (const float*)p_el2, (const float*)p_er2, b2, out, N);
}